// round 4
// baseline (speedup 1.0000x reference)
#include <cuda_runtime.h>
#include <cstdint>

#define NN     6144
#define MAXDEG 192
#define FULL   0xffffffffu
#define GRID1  768   // K1: warp per node
#define GRID2  384   // attn: 2 nodes per warp, 16 nodes per block

// ---------------- scratch (device globals; no allocation allowed) -----------
__device__ int   g_deg[NN];
__device__ int   g_cols[NN * MAXDEG];
// layer0 row stride 16: [h0..h11, ed0, ed1, es0, es1]
// layer1 row stride 12: [h0..h5, ed0, ed1, es0, es1, pad, pad]
// layer2 row stride 20: [h0..h15, ed, es, pad, pad]
__device__ __align__(16) float g_h0[NN * 16];
__device__ __align__(16) float g_h1[NN * 12];
__device__ __align__(16) float g_h2[NN * 20];
__device__ float g_part[GRID2 * 16];
__device__ int   g_counter;   // zero-initialized

#define XOR_RED(v) { _Pragma("unroll") for (int _o = 16; _o > 0; _o >>= 1) (v) += __shfl_xor_sync(FULL, (v), _o); }

// ===================== K1: linear0 + CSR build (fused) =======================
__global__ void __launch_bounds__(256) k_csr_lin0(
    const float* __restrict__ x, const float* __restrict__ adj,
    const float* __restrict__ W0, const float* __restrict__ a0s,
    const float* __restrict__ a0d)
{
    __shared__ float sW[64 * 12];
    __shared__ float sa[24];
    for (int i = threadIdx.x; i < 768; i += 256) sW[i] = W0[i];
    if (threadIdx.x < 12) {
        sa[threadIdx.x]      = a0s[threadIdx.x];
        sa[12 + threadIdx.x] = a0d[threadIdx.x];
    }
    __syncthreads();

    const int node = (blockIdx.x * 256 + threadIdx.x) >> 5;
    const int lane = threadIdx.x & 31;

    // ---- linear0 ----
    float x0 = x[node * 64 + lane];
    float x1 = x[node * 64 + 32 + lane];
    float acc[12];
#pragma unroll
    for (int h = 0; h < 2; h++)
#pragma unroll
        for (int f = 0; f < 6; f++) {
            int hf = h * 6 + f;
            acc[hf] = x0 * sW[(h * 64 + lane) * 6 + f]
                    + x1 * sW[(h * 64 + lane + 32) * 6 + f];
        }
#pragma unroll
    for (int i = 0; i < 12; i++) XOR_RED(acc[i]);

    if (lane == 0) {
        float es0 = 0.f, ed0 = 0.f, es1 = 0.f, ed1 = 0.f;
#pragma unroll
        for (int f = 0; f < 6; f++) {
            es0 += acc[f]     * sa[f];       ed0 += acc[f]     * sa[12 + f];
            es1 += acc[6 + f] * sa[6 + f];   ed1 += acc[6 + f] * sa[18 + f];
        }
        float4* row = reinterpret_cast<float4*>(&g_h0[node * 16]);
        row[0] = make_float4(acc[0], acc[1], acc[2],  acc[3]);
        row[1] = make_float4(acc[4], acc[5], acc[6],  acc[7]);
        row[2] = make_float4(acc[8], acc[9], acc[10], acc[11]);
        row[3] = make_float4(ed0, ed1, es0, es1);
    }

    // ---- CSR build with empty-chunk early skip ----
    const float4* a4 = reinterpret_cast<const float4*>(adj + (size_t)node * NN);
    int* outc = g_cols + (size_t)node * MAXDEG;
    int base = 0;
    const unsigned lt = (1u << lane) - 1u;
    float4 v = __ldg(&a4[lane]);
    for (int c0 = 0; c0 < NN; c0 += 128) {
        float4 vn = {0.f, 0.f, 0.f, 0.f};
        if (c0 + 128 < NN) vn = __ldg(&a4[((c0 + 128) >> 2) + lane]);
        bool n0 = v.x > 0.f, n1 = v.y > 0.f, n2 = v.z > 0.f, n3 = v.w > 0.f;
        unsigned any = __ballot_sync(FULL, n0 | n1 | n2 | n3);
        if (any) {
            int col0 = c0 + lane * 4;
            bool nz[4] = {n0, n1, n2, n3};
#pragma unroll
            for (int j = 0; j < 4; j++) {
                unsigned m = __ballot_sync(FULL, nz[j]);
                if (m) {
                    if (nz[j]) {
                        int p = base + __popc(m & lt);
                        if (p < MAXDEG) outc[p] = col0 + j;
                    }
                    base += __popc(m);
                }
            }
        }
        v = vn;
    }
    if (lane == 0) g_deg[node] = base < MAXDEG ? base : MAXDEG;
}

// ======== K2: attn layer0 (H=2,F=6) + elu + linear1 -> g_h1 ==================
// 16 lanes per node (feature-parallel), 2 nodes per warp.
__global__ void __launch_bounds__(256) k_attn0(
    const float* __restrict__ W1, const float* __restrict__ a1s,
    const float* __restrict__ a1d)
{
    __shared__ float sW[72];        // [2][12][3]
    __shared__ float sa[12];
    __shared__ float shx[8][2][16]; // elu outputs per node
    __shared__ float shh[8][2][8];  // new-layer h per node
    if (threadIdx.x < 72) sW[threadIdx.x] = W1[threadIdx.x];
    if (threadIdx.x < 6) {
        sa[threadIdx.x]     = a1s[threadIdx.x];
        sa[6 + threadIdx.x] = a1d[threadIdx.x];
    }
    __syncthreads();

    const int lane = threadIdx.x & 31;
    const int wid  = threadIdx.x >> 5;
    const int half = lane >> 4;
    const int fl   = lane & 15;
    const int node = (blockIdx.x * 8 + wid) * 2 + half;
    const int deg  = g_deg[node];
    const int* __restrict__ cols = g_cols + (size_t)node * MAXDEG;

    const float es0 = g_h0[node * 16 + 14];
    const float es1 = g_h0[node * 16 + 15];
    const int degmax = max(deg, __shfl_xor_sync(FULL, deg, 16));

    float acc = 0.f, ws0 = 0.f, ws1 = 0.f;
#pragma unroll 4
    for (int k = 0; k < degmax; k++) {
        int kk = k < deg ? k : deg - 1;
        int m = cols[kk];
        float hv = g_h0[m * 16 + fl];
        float ed0 = __shfl_sync(FULL, hv, 12, 16);
        float ed1 = __shfl_sync(FULL, hv, 13, 16);
        float e0 = es0 + ed0; e0 = e0 > 0.f ? e0 : 0.2f * e0;
        float e1 = es1 + ed1; e1 = e1 > 0.f ? e1 : 0.2f * e1;
        float w0 = __expf(e0), w1 = __expf(e1);
        if (k < deg) {
            ws0 += w0; ws1 += w1;
            acc += (fl < 6 ? w0 : w1) * hv;
        }
    }
    float vv = acc * (1.f / (fl < 6 ? ws0 : ws1));
    shx[wid][half][fl] = vv > 0.f ? vv : expm1f(vv);
    __syncwarp();
    if (fl < 6) {
        int h2 = fl / 3, f2 = fl % 3;
        float s = 0.f;
#pragma unroll
        for (int i = 0; i < 12; i++) s += shx[wid][half][i] * sW[(h2 * 12 + i) * 3 + f2];
        g_h1[node * 12 + fl] = s;
        shh[wid][half][fl] = s;
    }
    __syncwarp();
    if (fl < 2) {
        float es = 0.f, ed = 0.f;
#pragma unroll
        for (int f2 = 0; f2 < 3; f2++) {
            float hv = shh[wid][half][fl * 3 + f2];
            es += hv * sa[fl * 3 + f2];
            ed += hv * sa[6 + fl * 3 + f2];
        }
        g_h1[node * 12 + 6 + fl] = ed;
        g_h1[node * 12 + 8 + fl] = es;
    }
}

// ======== K3: attn layer1 (H=2,F=3) + elu + linear2 -> g_h2 ==================
__global__ void __launch_bounds__(256) k_attn1(
    const float* __restrict__ W2, const float* __restrict__ a2s,
    const float* __restrict__ a2d)
{
    __shared__ float sW[96];        // [6][16]
    __shared__ float sa2[32];       // a2d(16), a2s(16)
    __shared__ float shx[8][2][8];
    __shared__ float shh[8][2][16];
    if (threadIdx.x < 96) sW[threadIdx.x] = W2[threadIdx.x];
    if (threadIdx.x < 16) {
        sa2[threadIdx.x]      = a2d[threadIdx.x];
        sa2[16 + threadIdx.x] = a2s[threadIdx.x];
    }
    __syncthreads();

    const int lane = threadIdx.x & 31;
    const int wid  = threadIdx.x >> 5;
    const int half = lane >> 4;
    const int fl   = lane & 15;
    const int node = (blockIdx.x * 8 + wid) * 2 + half;
    const int deg  = g_deg[node];
    const int* __restrict__ cols = g_cols + (size_t)node * MAXDEG;

    const float es0 = g_h1[node * 12 + 8];
    const float es1 = g_h1[node * 12 + 9];
    const int degmax = max(deg, __shfl_xor_sync(FULL, deg, 16));

    float acc = 0.f, ws0 = 0.f, ws1 = 0.f;
#pragma unroll 4
    for (int k = 0; k < degmax; k++) {
        int kk = k < deg ? k : deg - 1;
        int m = cols[kk];
        float hv = fl < 12 ? g_h1[m * 12 + fl] : 0.f;
        float ed0 = __shfl_sync(FULL, hv, 6, 16);
        float ed1 = __shfl_sync(FULL, hv, 7, 16);
        float e0 = es0 + ed0; e0 = e0 > 0.f ? e0 : 0.2f * e0;
        float e1 = es1 + ed1; e1 = e1 > 0.f ? e1 : 0.2f * e1;
        float w0 = __expf(e0), w1 = __expf(e1);
        if (k < deg) {
            ws0 += w0; ws1 += w1;
            acc += (fl < 3 ? w0 : w1) * hv;
        }
    }
    if (fl < 6) {
        float vv = acc * (1.f / (fl < 3 ? ws0 : ws1));
        shx[wid][half][fl] = vv > 0.f ? vv : expm1f(vv);
    }
    __syncwarp();
    {   // 16 output features, one per lane
        float s = 0.f;
#pragma unroll
        for (int i = 0; i < 6; i++) s += shx[wid][half][i] * sW[i * 16 + fl];
        g_h2[node * 20 + fl] = s;
        shh[wid][half][fl] = s;
    }
    __syncwarp();
    if (fl < 2) {
        float d = 0.f;
#pragma unroll
        for (int f = 0; f < 16; f++) d += shh[wid][half][f] * sa2[fl * 16 + f];
        g_h2[node * 20 + 16 + fl] = d;   // 16 = ed, 17 = es
    }
}

// ===== K4: final attn (H=1,F=16) + relu + hierarchical deterministic sum =====
__global__ void __launch_bounds__(256) k_attn_final(float* __restrict__ out)
{
    __shared__ float sblk[16][16];   // 16 nodes per block
    const int lane = threadIdx.x & 31;
    const int wid  = threadIdx.x >> 5;
    const int half = lane >> 4;
    const int fl   = lane & 15;
    const int node = (blockIdx.x * 8 + wid) * 2 + half;
    const int deg  = g_deg[node];
    const int* __restrict__ cols = g_cols + (size_t)node * MAXDEG;

    const float es = g_h2[node * 20 + 17];
    const int degmax = max(deg, __shfl_xor_sync(FULL, deg, 16));

    float acc = 0.f, ws = 0.f;
#pragma unroll 4
    for (int k = 0; k < degmax; k++) {
        int kk = k < deg ? k : deg - 1;
        int m = cols[kk];
        float hv = g_h2[m * 20 + fl];
        float ed = g_h2[m * 20 + 16];     // broadcast within half
        float e = es + ed; e = e > 0.f ? e : 0.2f * e;
        float w = __expf(e);
        if (k < deg) { ws += w; acc += w * hv; }
    }
    float v = acc * (1.f / ws);
    sblk[wid * 2 + half][fl] = v > 0.f ? v : 0.f;
    __syncthreads();

    // per-block partial: 16 nodes -> 16 floats (fixed order)
    if (threadIdx.x < 16) {
        float p = 0.f;
#pragma unroll
        for (int w = 0; w < 16; w++) p += sblk[w][threadIdx.x];
        g_part[blockIdx.x * 16 + threadIdx.x] = p;
    }
    __threadfence();
    __syncthreads();
    __shared__ bool isLast;
    if (threadIdx.x == 0)
        isLast = (atomicAdd(&g_counter, 1) == GRID2 - 1);
    __syncthreads();
    if (isLast) {
        __threadfence();
        int f = threadIdx.x & 15, g = threadIdx.x >> 4;
        float s = 0.f;
        for (int b = g; b < GRID2; b += 16) s += g_part[b * 16 + f];
        __shared__ float red2[256];
        red2[threadIdx.x] = s;
        __syncthreads();
        if (threadIdx.x < 16) {
            float t = 0.f;
#pragma unroll
            for (int gg = 0; gg < 16; gg++) t += red2[gg * 16 + threadIdx.x];
            out[threadIdx.x] = t;
        }
        if (threadIdx.x == 0) g_counter = 0;   // reset for next replay
    }
}

// ---------------- launch ----------------------------------------------------
extern "C" void kernel_launch(void* const* d_in, const int* in_sizes, int n_in,
                              void* d_out, int out_size) {
    const float* x   = (const float*)d_in[0];
    const float* adj = (const float*)d_in[1];
    const float* W0  = (const float*)d_in[2];
    const float* a0s = (const float*)d_in[3];
    const float* a0d = (const float*)d_in[4];
    const float* W1  = (const float*)d_in[5];
    const float* a1s = (const float*)d_in[6];
    const float* a1d = (const float*)d_in[7];
    const float* W2  = (const float*)d_in[8];
    const float* a2s = (const float*)d_in[9];
    const float* a2d = (const float*)d_in[10];
    float* out = (float*)d_out;

    k_csr_lin0  <<<GRID1, 256>>>(x, adj, W0, a0s, a0d);
    k_attn0     <<<GRID2, 256>>>(W1, a1s, a1d);
    k_attn1     <<<GRID2, 256>>>(W2, a2s, a2d);
    k_attn_final<<<GRID2, 256>>>(out);
}

// round 5
// speedup vs baseline: 1.2903x; 1.2903x over previous
#include <cuda_runtime.h>
#include <cstdint>

#define NN     6144
#define MAXDEG 192
#define FULL   0xffffffffu
#define GRID1  768   // warp per node everywhere

// ---------------- scratch (device globals; no allocation allowed) -----------
__device__ int   g_deg[NN];
__device__ int   g_cols[NN * MAXDEG];
// layer0 row stride 16: [h0..h11, ed0, ed1, es0, es1]
// layer1 row stride 12: [h0..h5, ed0, ed1, es0, es1, pad, pad]
// layer2 row stride 20: [h0..h15, ed, es, pad, pad]
__device__ __align__(16) float g_h0[NN * 16];
__device__ __align__(16) float g_h1[NN * 12];
__device__ __align__(16) float g_h2[NN * 20];
__device__ float g_part[GRID1 * 16];
__device__ int   g_counter;   // zero-initialized

#define XOR_RED(v) { _Pragma("unroll") for (int _o = 16; _o > 0; _o >>= 1) (v) += __shfl_xor_sync(FULL, (v), _o); }

// ===================== K1: linear0 + CSR build (fused) =======================
__global__ void __launch_bounds__(256) k_csr_lin0(
    const float* __restrict__ x, const float* __restrict__ adj,
    const float* __restrict__ W0, const float* __restrict__ a0s,
    const float* __restrict__ a0d)
{
    __shared__ float sW[64 * 12];
    __shared__ float sa[24];
    for (int i = threadIdx.x; i < 768; i += 256) sW[i] = W0[i];
    if (threadIdx.x < 12) {
        sa[threadIdx.x]      = a0s[threadIdx.x];
        sa[12 + threadIdx.x] = a0d[threadIdx.x];
    }
    __syncthreads();

    const int node = (blockIdx.x * 256 + threadIdx.x) >> 5;
    const int lane = threadIdx.x & 31;

    // ---- linear0 ----
    float x0 = x[node * 64 + lane];
    float x1 = x[node * 64 + 32 + lane];
    float acc[12];
#pragma unroll
    for (int h = 0; h < 2; h++)
#pragma unroll
        for (int f = 0; f < 6; f++) {
            int hf = h * 6 + f;
            acc[hf] = x0 * sW[(h * 64 + lane) * 6 + f]
                    + x1 * sW[(h * 64 + lane + 32) * 6 + f];
        }
#pragma unroll
    for (int i = 0; i < 12; i++) XOR_RED(acc[i]);

    if (lane == 0) {
        float es0 = 0.f, ed0 = 0.f, es1 = 0.f, ed1 = 0.f;
#pragma unroll
        for (int f = 0; f < 6; f++) {
            es0 += acc[f]     * sa[f];       ed0 += acc[f]     * sa[12 + f];
            es1 += acc[6 + f] * sa[6 + f];   ed1 += acc[6 + f] * sa[18 + f];
        }
        float4* row = reinterpret_cast<float4*>(&g_h0[node * 16]);
        row[0] = make_float4(acc[0], acc[1], acc[2],  acc[3]);
        row[1] = make_float4(acc[4], acc[5], acc[6],  acc[7]);
        row[2] = make_float4(acc[8], acc[9], acc[10], acc[11]);
        row[3] = make_float4(ed0, ed1, es0, es1);
    }

    // ---- CSR build: 256 cols per iteration, 2 float4 in flight -------------
    const float4* a4 = reinterpret_cast<const float4*>(adj + (size_t)node * NN);
    int* outc = g_cols + (size_t)node * MAXDEG;
    int base = 0;
    const unsigned lt = (1u << lane) - 1u;
    float4 va = __ldg(&a4[lane]);
    float4 vb = __ldg(&a4[32 + lane]);
    for (int c0 = 0; c0 < NN; c0 += 256) {
        float4 na = {0,0,0,0}, nb = {0,0,0,0};
        if (c0 + 256 < NN) {
            na = __ldg(&a4[((c0 + 256) >> 2) + lane]);
            nb = __ldg(&a4[((c0 + 256) >> 2) + 32 + lane]);
        }
#pragma unroll
        for (int s = 0; s < 2; s++) {
            float4 v = s == 0 ? va : vb;
            bool n0 = v.x > 0.f, n1 = v.y > 0.f, n2 = v.z > 0.f, n3 = v.w > 0.f;
            unsigned any = __ballot_sync(FULL, n0 | n1 | n2 | n3);
            if (any) {
                int col0 = c0 + s * 128 + lane * 4;
                bool nz[4] = {n0, n1, n2, n3};
#pragma unroll
                for (int j = 0; j < 4; j++) {
                    unsigned m = __ballot_sync(FULL, nz[j]);
                    if (m) {
                        if (nz[j]) {
                            int p = base + __popc(m & lt);
                            if (p < MAXDEG) outc[p] = col0 + j;
                        }
                        base += __popc(m);
                    }
                }
            }
        }
        va = na; vb = nb;
    }
    if (lane == 0) g_deg[node] = base < MAXDEG ? base : MAXDEG;
}

// ======== K2: attn layer0 (H=2,F=6) + elu + linear1 -> g_h1 ==================
// Warp per node; 2 neighbors x 16 features per iteration.
__global__ void __launch_bounds__(256) k_attn0(
    const float* __restrict__ W1, const float* __restrict__ a1s,
    const float* __restrict__ a1d)
{
    __shared__ float sW[72];        // [2][12][3]
    __shared__ float sa[12];
    __shared__ float shx[8][16];
    __shared__ float shh[8][8];
    if (threadIdx.x < 72) sW[threadIdx.x] = W1[threadIdx.x];
    if (threadIdx.x < 6) {
        sa[threadIdx.x]     = a1s[threadIdx.x];
        sa[6 + threadIdx.x] = a1d[threadIdx.x];
    }
    __syncthreads();

    const int lane = threadIdx.x & 31;
    const int wid  = threadIdx.x >> 5;
    const int j    = lane >> 4;
    const int fl   = lane & 15;
    const int node = (blockIdx.x * 256 + threadIdx.x) >> 5;
    const int deg  = g_deg[node];
    const int* __restrict__ cols = g_cols + (size_t)node * MAXDEG;

    const float es0 = g_h0[node * 16 + 14];
    const float es1 = g_h0[node * 16 + 15];

    float acc = 0.f, ws0 = 0.f, ws1 = 0.f;
#pragma unroll 4
    for (int kb = 0; kb < deg; kb += 2) {
        int k = kb + j;
        bool valid = k < deg;
        int m = cols[valid ? k : deg - 1];
        float hv = g_h0[m * 16 + fl];
        float ed0 = __shfl_sync(FULL, hv, 12, 16);
        float ed1 = __shfl_sync(FULL, hv, 13, 16);
        float e0 = es0 + ed0; e0 = e0 > 0.f ? e0 : 0.2f * e0;
        float e1 = es1 + ed1; e1 = e1 > 0.f ? e1 : 0.2f * e1;
        float w0 = __expf(e0), w1 = __expf(e1);
        if (valid) {
            ws0 += w0; ws1 += w1;
            acc += (fl < 6 ? w0 : w1) * hv;
        }
    }
    acc += __shfl_xor_sync(FULL, acc, 16);
    ws0 += __shfl_xor_sync(FULL, ws0, 16);
    ws1 += __shfl_xor_sync(FULL, ws1, 16);

    if (lane < 12) {
        float vv = acc * (1.f / (lane < 6 ? ws0 : ws1));
        shx[wid][lane] = vv > 0.f ? vv : expm1f(vv);
    }
    __syncwarp();
    if (lane < 6) {
        int h2 = lane / 3, f2 = lane % 3;
        float s = 0.f;
#pragma unroll
        for (int i = 0; i < 12; i++) s += shx[wid][i] * sW[(h2 * 12 + i) * 3 + f2];
        g_h1[node * 12 + lane] = s;
        shh[wid][lane] = s;
    }
    __syncwarp();
    if (lane < 2) {
        float es = 0.f, ed = 0.f;
#pragma unroll
        for (int f2 = 0; f2 < 3; f2++) {
            float hv = shh[wid][lane * 3 + f2];
            es += hv * sa[lane * 3 + f2];
            ed += hv * sa[6 + lane * 3 + f2];
        }
        g_h1[node * 12 + 6 + lane] = ed;
        g_h1[node * 12 + 8 + lane] = es;
    }
}

// ======== K3: attn layer1 (H=2,F=3) + elu + linear2 -> g_h2 ==================
// Warp per node; 4 neighbors x 8 features per iteration.
__global__ void __launch_bounds__(256) k_attn1(
    const float* __restrict__ W2, const float* __restrict__ a2s,
    const float* __restrict__ a2d)
{
    __shared__ float sW[96];        // [6][16]
    __shared__ float sa2[32];       // a2d(16), a2s(16)
    __shared__ float shx[8][8];
    __shared__ float shh[8][16];
    if (threadIdx.x < 96) sW[threadIdx.x] = W2[threadIdx.x];
    if (threadIdx.x < 16) {
        sa2[threadIdx.x]      = a2d[threadIdx.x];
        sa2[16 + threadIdx.x] = a2s[threadIdx.x];
    }
    __syncthreads();

    const int lane = threadIdx.x & 31;
    const int wid  = threadIdx.x >> 5;
    const int j    = lane >> 3;       // 0..3
    const int fl   = lane & 7;        // 0..7
    const int node = (blockIdx.x * 256 + threadIdx.x) >> 5;
    const int deg  = g_deg[node];
    const int* __restrict__ cols = g_cols + (size_t)node * MAXDEG;

    const float es0 = g_h1[node * 12 + 8];
    const float es1 = g_h1[node * 12 + 9];

    float acc = 0.f, ws0 = 0.f, ws1 = 0.f;
#pragma unroll 4
    for (int kb = 0; kb < deg; kb += 4) {
        int k = kb + j;
        bool valid = k < deg;
        int m = cols[valid ? k : deg - 1];
        float hv = g_h1[m * 12 + fl];     // fl 0..5 = h, 6,7 = ed0,ed1
        float ed0 = __shfl_sync(FULL, hv, 6, 8);
        float ed1 = __shfl_sync(FULL, hv, 7, 8);
        float e0 = es0 + ed0; e0 = e0 > 0.f ? e0 : 0.2f * e0;
        float e1 = es1 + ed1; e1 = e1 > 0.f ? e1 : 0.2f * e1;
        float w0 = __expf(e0), w1 = __expf(e1);
        if (valid) {
            ws0 += w0; ws1 += w1;
            acc += (fl < 3 ? w0 : w1) * hv;
        }
    }
    acc += __shfl_xor_sync(FULL, acc, 8);
    acc += __shfl_xor_sync(FULL, acc, 16);
    ws0 += __shfl_xor_sync(FULL, ws0, 8);
    ws0 += __shfl_xor_sync(FULL, ws0, 16);
    ws1 += __shfl_xor_sync(FULL, ws1, 8);
    ws1 += __shfl_xor_sync(FULL, ws1, 16);

    if (lane < 6) {
        float vv = acc * (1.f / (lane < 3 ? ws0 : ws1));
        shx[wid][lane] = vv > 0.f ? vv : expm1f(vv);
    }
    __syncwarp();
    if (lane < 16) {
        float s = 0.f;
#pragma unroll
        for (int i = 0; i < 6; i++) s += shx[wid][i] * sW[i * 16 + lane];
        g_h2[node * 20 + lane] = s;
        shh[wid][lane] = s;
    }
    __syncwarp();
    if (lane < 2) {
        float d = 0.f;
#pragma unroll
        for (int f = 0; f < 16; f++) d += shh[wid][f] * sa2[lane * 16 + f];
        g_h2[node * 20 + 16 + lane] = d;   // 16 = ed, 17 = es
    }
}

// ===== K4: final attn (H=1,F=16) + relu + hierarchical deterministic sum =====
// Warp per node; 2 neighbors x 16 features per iteration.
__global__ void __launch_bounds__(256) k_attn_final(float* __restrict__ out)
{
    __shared__ float sblk[8][16];
    const int lane = threadIdx.x & 31;
    const int wid  = threadIdx.x >> 5;
    const int j    = lane >> 4;
    const int fl   = lane & 15;
    const int node = (blockIdx.x * 256 + threadIdx.x) >> 5;
    const int deg  = g_deg[node];
    const int* __restrict__ cols = g_cols + (size_t)node * MAXDEG;

    const float es = g_h2[node * 20 + 17];

    float acc = 0.f, ws = 0.f;
#pragma unroll 4
    for (int kb = 0; kb < deg; kb += 2) {
        int k = kb + j;
        bool valid = k < deg;
        int m = cols[valid ? k : deg - 1];
        float hv = g_h2[m * 20 + fl];
        float ed = g_h2[m * 20 + 16];     // broadcast within 16-group
        float e = es + ed; e = e > 0.f ? e : 0.2f * e;
        float w = __expf(e);
        if (valid) { ws += w; acc += w * hv; }
    }
    acc += __shfl_xor_sync(FULL, acc, 16);
    ws  += __shfl_xor_sync(FULL, ws, 16);

    if (j == 0) {
        float v = acc * (1.f / ws);
        sblk[wid][fl] = v > 0.f ? v : 0.f;
    }
    __syncthreads();

    // per-block partial: 8 nodes -> 16 floats (fixed order)
    if (threadIdx.x < 16) {
        float p = 0.f;
#pragma unroll
        for (int w = 0; w < 8; w++) p += sblk[w][threadIdx.x];
        g_part[blockIdx.x * 16 + threadIdx.x] = p;
    }
    __threadfence();
    __syncthreads();
    __shared__ bool isLast;
    if (threadIdx.x == 0)
        isLast = (atomicAdd(&g_counter, 1) == GRID1 - 1);
    __syncthreads();
    if (isLast) {
        __threadfence();
        int f = threadIdx.x & 15, g = threadIdx.x >> 4;
        float s = 0.f;
        for (int b = g; b < GRID1; b += 16) s += g_part[b * 16 + f];
        __shared__ float red2[256];
        red2[threadIdx.x] = s;
        __syncthreads();
        if (threadIdx.x < 16) {
            float t = 0.f;
#pragma unroll
            for (int gg = 0; gg < 16; gg++) t += red2[gg * 16 + threadIdx.x];
            out[threadIdx.x] = t;
        }
        if (threadIdx.x == 0) g_counter = 0;   // reset for next replay
    }
}

// ---------------- launch ----------------------------------------------------
extern "C" void kernel_launch(void* const* d_in, const int* in_sizes, int n_in,
                              void* d_out, int out_size) {
    const float* x   = (const float*)d_in[0];
    const float* adj = (const float*)d_in[1];
    const float* W0  = (const float*)d_in[2];
    const float* a0s = (const float*)d_in[3];
    const float* a0d = (const float*)d_in[4];
    const float* W1  = (const float*)d_in[5];
    const float* a1s = (const float*)d_in[6];
    const float* a1d = (const float*)d_in[7];
    const float* W2  = (const float*)d_in[8];
    const float* a2s = (const float*)d_in[9];
    const float* a2d = (const float*)d_in[10];
    float* out = (float*)d_out;

    k_csr_lin0  <<<GRID1, 256>>>(x, adj, W0, a0s, a0d);
    k_attn0     <<<GRID1, 256>>>(W1, a1s, a1d);
    k_attn1     <<<GRID1, 256>>>(W2, a2s, a2d);
    k_attn_final<<<GRID1, 256>>>(out);
}

// round 6
// speedup vs baseline: 1.4447x; 1.1196x over previous
#include <cuda_runtime.h>
#include <cstdint>

#define NN     6144
#define MAXDEG 192
#define FULL   0xffffffffu
#define GRID1  768   // warp per node everywhere

// ---------------- scratch (device globals; no allocation allowed) -----------
__device__ int   g_deg[NN];
__device__ int   g_cols[NN * MAXDEG];
// layer0 row stride 16: [h0..h11, ed0, ed1, es0, es1]
// layer1 row stride 12: [h0..h5, ed0, ed1, es0, es1, pad, pad]
// layer2 row stride 20: [h0..h15, ed, es, pad, pad]
__device__ __align__(16) float g_h0[NN * 16];
__device__ __align__(16) float g_h1[NN * 12];
__device__ __align__(16) float g_h2[NN * 20];
__device__ float g_part[GRID1 * 16];
__device__ int   g_counter;   // zero-initialized

#define XOR_RED(v) { _Pragma("unroll") for (int _o = 16; _o > 0; _o >>= 1) (v) += __shfl_xor_sync(FULL, (v), _o); }

// ===================== K1: linear0 + CSR build (fused) =======================
__global__ void __launch_bounds__(256) k_csr_lin0(
    const float* __restrict__ x, const float* __restrict__ adj,
    const float* __restrict__ W0, const float* __restrict__ a0s,
    const float* __restrict__ a0d)
{
    __shared__ float sW[64 * 12];
    __shared__ float sa[24];
    for (int i = threadIdx.x; i < 768; i += 256) sW[i] = W0[i];
    if (threadIdx.x < 12) {
        sa[threadIdx.x]      = a0s[threadIdx.x];
        sa[12 + threadIdx.x] = a0d[threadIdx.x];
    }
    __syncthreads();

    const int node = (blockIdx.x * 256 + threadIdx.x) >> 5;
    const int lane = threadIdx.x & 31;

    // ---- linear0 ----
    float x0 = x[node * 64 + lane];
    float x1 = x[node * 64 + 32 + lane];
    float acc[12];
#pragma unroll
    for (int h = 0; h < 2; h++)
#pragma unroll
        for (int f = 0; f < 6; f++) {
            int hf = h * 6 + f;
            acc[hf] = x0 * sW[(h * 64 + lane) * 6 + f]
                    + x1 * sW[(h * 64 + lane + 32) * 6 + f];
        }
#pragma unroll
    for (int i = 0; i < 12; i++) XOR_RED(acc[i]);

    if (lane == 0) {
        float es0 = 0.f, ed0 = 0.f, es1 = 0.f, ed1 = 0.f;
#pragma unroll
        for (int f = 0; f < 6; f++) {
            es0 += acc[f]     * sa[f];       ed0 += acc[f]     * sa[12 + f];
            es1 += acc[6 + f] * sa[6 + f];   ed1 += acc[6 + f] * sa[18 + f];
        }
        float4* row = reinterpret_cast<float4*>(&g_h0[node * 16]);
        row[0] = make_float4(acc[0], acc[1], acc[2],  acc[3]);
        row[1] = make_float4(acc[4], acc[5], acc[6],  acc[7]);
        row[2] = make_float4(acc[8], acc[9], acc[10], acc[11]);
        row[3] = make_float4(ed0, ed1, es0, es1);
    }

    // ---- CSR build: 256 cols per iteration, 2 float4 in flight -------------
    const float4* a4 = reinterpret_cast<const float4*>(adj + (size_t)node * NN);
    int* outc = g_cols + (size_t)node * MAXDEG;
    int base = 0;
    const unsigned lt = (1u << lane) - 1u;
    float4 va = __ldg(&a4[lane]);
    float4 vb = __ldg(&a4[32 + lane]);
    for (int c0 = 0; c0 < NN; c0 += 256) {
        float4 na = {0,0,0,0}, nb = {0,0,0,0};
        if (c0 + 256 < NN) {
            na = __ldg(&a4[((c0 + 256) >> 2) + lane]);
            nb = __ldg(&a4[((c0 + 256) >> 2) + 32 + lane]);
        }
#pragma unroll
        for (int s = 0; s < 2; s++) {
            float4 v = s == 0 ? va : vb;
            bool n0 = v.x > 0.f, n1 = v.y > 0.f, n2 = v.z > 0.f, n3 = v.w > 0.f;
            unsigned any = __ballot_sync(FULL, n0 | n1 | n2 | n3);
            if (any) {
                int col0 = c0 + s * 128 + lane * 4;
                bool nz[4] = {n0, n1, n2, n3};
#pragma unroll
                for (int j = 0; j < 4; j++) {
                    unsigned m = __ballot_sync(FULL, nz[j]);
                    if (m) {
                        if (nz[j]) {
                            int p = base + __popc(m & lt);
                            if (p < MAXDEG) outc[p] = col0 + j;
                        }
                        base += __popc(m);
                    }
                }
            }
        }
        va = na; vb = nb;
    }
    if (lane == 0) g_deg[node] = base < MAXDEG ? base : MAXDEG;
}

// ======== K2: attn layer0 (H=2,F=6) + elu + linear1 -> g_h1 ==================
// Warp per node; 4 neighbors x 8 float2-lanes per iteration.
__global__ void __launch_bounds__(256) k_attn0(
    const float* __restrict__ W1, const float* __restrict__ a1s,
    const float* __restrict__ a1d)
{
    __shared__ float sW[72];        // [2][12][3]
    __shared__ float sa[12];
    __shared__ float shx[8][16];
    __shared__ float shh[8][8];
    __shared__ int   scols[8][MAXDEG];
    if (threadIdx.x < 72) sW[threadIdx.x] = W1[threadIdx.x];
    if (threadIdx.x < 6) {
        sa[threadIdx.x]     = a1s[threadIdx.x];
        sa[6 + threadIdx.x] = a1d[threadIdx.x];
    }
    __syncthreads();

    const int lane = threadIdx.x & 31;
    const int wid  = threadIdx.x >> 5;
    const int j    = lane >> 3;        // 0..3 neighbor slot
    const int fl   = lane & 7;         // float2 feature slot (features 2fl,2fl+1)
    const int node = (blockIdx.x * 256 + threadIdx.x) >> 5;
    const int deg  = g_deg[node];
    const int* __restrict__ cols = g_cols + (size_t)node * MAXDEG;

    for (int k = lane; k < deg; k += 32) scols[wid][k] = cols[k];
    __syncwarp();

    const float es0 = g_h0[node * 16 + 14];
    const float es1 = g_h0[node * 16 + 15];

    float ax = 0.f, ay = 0.f, ws0 = 0.f, ws1 = 0.f;
#pragma unroll 4
    for (int kb = 0; kb < deg; kb += 4) {
        int k = kb + j;
        bool valid = k < deg;
        int m = scols[wid][valid ? k : deg - 1];
        float2 hv = *reinterpret_cast<const float2*>(&g_h0[m * 16 + fl * 2]);
        float ed0 = __shfl_sync(FULL, hv.x, 6, 8);   // feature 12
        float ed1 = __shfl_sync(FULL, hv.y, 6, 8);   // feature 13
        float e0 = es0 + ed0; e0 = e0 > 0.f ? e0 : 0.2f * e0;
        float e1 = es1 + ed1; e1 = e1 > 0.f ? e1 : 0.2f * e1;
        float w0 = __expf(e0), w1 = __expf(e1);
        if (valid) {
            ws0 += w0; ws1 += w1;
            float w = fl < 3 ? w0 : w1;   // features 2fl,2fl+1 same head
            ax += w * hv.x; ay += w * hv.y;
        }
    }
    // merge across neighbor slots (bits 3,4)
#pragma unroll
    for (int o = 8; o <= 16; o <<= 1) {
        ax  += __shfl_xor_sync(FULL, ax, o);
        ay  += __shfl_xor_sync(FULL, ay, o);
        ws0 += __shfl_xor_sync(FULL, ws0, o);
        ws1 += __shfl_xor_sync(FULL, ws1, o);
    }

    if (lane < 6) {   // j==0 lanes, features 2fl,2fl+1 < 12
        float inv = 1.f / (fl < 3 ? ws0 : ws1);
        float vx = ax * inv, vy = ay * inv;
        shx[wid][fl * 2]     = vx > 0.f ? vx : expm1f(vx);
        shx[wid][fl * 2 + 1] = vy > 0.f ? vy : expm1f(vy);
    }
    __syncwarp();
    if (lane < 6) {
        int h2 = lane / 3, f2 = lane % 3;
        float s = 0.f;
#pragma unroll
        for (int i = 0; i < 12; i++) s += shx[wid][i] * sW[(h2 * 12 + i) * 3 + f2];
        g_h1[node * 12 + lane] = s;
        shh[wid][lane] = s;
    }
    __syncwarp();
    if (lane < 2) {
        float es = 0.f, ed = 0.f;
#pragma unroll
        for (int f2 = 0; f2 < 3; f2++) {
            float hv = shh[wid][lane * 3 + f2];
            es += hv * sa[lane * 3 + f2];
            ed += hv * sa[6 + lane * 3 + f2];
        }
        g_h1[node * 12 + 6 + lane] = ed;
        g_h1[node * 12 + 8 + lane] = es;
    }
}

// ======== K3: attn layer1 (H=2,F=3) + elu + linear2 -> g_h2 ==================
// Warp per node; 8 neighbors x 4 float2-lanes per iteration.
__global__ void __launch_bounds__(256) k_attn1(
    const float* __restrict__ W2, const float* __restrict__ a2s,
    const float* __restrict__ a2d)
{
    __shared__ float sW[96];        // [6][16]
    __shared__ float sa2[32];       // a2d(16), a2s(16)
    __shared__ float shx[8][8];
    __shared__ float shh[8][16];
    __shared__ int   scols[8][MAXDEG];
    if (threadIdx.x < 96) sW[threadIdx.x] = W2[threadIdx.x];
    if (threadIdx.x < 16) {
        sa2[threadIdx.x]      = a2d[threadIdx.x];
        sa2[16 + threadIdx.x] = a2s[threadIdx.x];
    }
    __syncthreads();

    const int lane = threadIdx.x & 31;
    const int wid  = threadIdx.x >> 5;
    const int j    = lane >> 2;        // 0..7 neighbor slot
    const int fl   = lane & 3;         // float2 slot (floats 2fl,2fl+1 of row)
    const int node = (blockIdx.x * 256 + threadIdx.x) >> 5;
    const int deg  = g_deg[node];
    const int* __restrict__ cols = g_cols + (size_t)node * MAXDEG;

    for (int k = lane; k < deg; k += 32) scols[wid][k] = cols[k];
    __syncwarp();

    const float es0 = g_h1[node * 12 + 8];
    const float es1 = g_h1[node * 12 + 9];

    float ax = 0.f, ay = 0.f, ws0 = 0.f, ws1 = 0.f;
#pragma unroll 4
    for (int kb = 0; kb < deg; kb += 8) {
        int k = kb + j;
        bool valid = k < deg;
        int m = scols[wid][valid ? k : deg - 1];
        float2 hv = *reinterpret_cast<const float2*>(&g_h1[m * 12 + fl * 2]);
        float ed0 = __shfl_sync(FULL, hv.x, 3, 4);   // float 6
        float ed1 = __shfl_sync(FULL, hv.y, 3, 4);   // float 7
        float e0 = es0 + ed0; e0 = e0 > 0.f ? e0 : 0.2f * e0;
        float e1 = es1 + ed1; e1 = e1 > 0.f ? e1 : 0.2f * e1;
        float w0 = __expf(e0), w1 = __expf(e1);
        if (valid) {
            ws0 += w0; ws1 += w1;
            // features: 2fl -> head (2fl<3 ? 0:1), 2fl+1 -> (2fl+1<3 ? 0:1)
            ax += (fl < 2 ? w0 : w1) * hv.x;   // f0,f2 head0; f4,f6 head1
            ay += (fl < 1 ? w0 : w1) * hv.y;   // f1 head0; f3,f5,f7 head1
        }
    }
#pragma unroll
    for (int o = 4; o <= 16; o <<= 1) {
        ax  += __shfl_xor_sync(FULL, ax, o);
        ay  += __shfl_xor_sync(FULL, ay, o);
        ws0 += __shfl_xor_sync(FULL, ws0, o);
        ws1 += __shfl_xor_sync(FULL, ws1, o);
    }

    if (lane < 3) {   // features 2fl,2fl+1 < 6
        float vx = ax * (1.f / (2 * lane     < 3 ? ws0 : ws1));
        float vy = ay * (1.f / (2 * lane + 1 < 3 ? ws0 : ws1));
        shx[wid][lane * 2]     = vx > 0.f ? vx : expm1f(vx);
        shx[wid][lane * 2 + 1] = vy > 0.f ? vy : expm1f(vy);
    }
    __syncwarp();
    if (lane < 16) {
        float s = 0.f;
#pragma unroll
        for (int i = 0; i < 6; i++) s += shx[wid][i] * sW[i * 16 + lane];
        g_h2[node * 20 + lane] = s;
        shh[wid][lane] = s;
    }
    __syncwarp();
    if (lane < 2) {
        float d = 0.f;
#pragma unroll
        for (int f = 0; f < 16; f++) d += shh[wid][f] * sa2[lane * 16 + f];
        g_h2[node * 20 + 16 + lane] = d;   // 16 = ed, 17 = es
    }
}

// ===== K4: final attn (H=1,F=16) + relu + hierarchical deterministic sum =====
// Warp per node; 4 neighbors x 8 float2-lanes per iteration.
__global__ void __launch_bounds__(256) k_attn_final(float* __restrict__ out)
{
    __shared__ float sblk[8][16];
    __shared__ int   scols[8][MAXDEG];
    const int lane = threadIdx.x & 31;
    const int wid  = threadIdx.x >> 5;
    const int j    = lane >> 3;        // 0..3
    const int fl   = lane & 7;         // features 2fl, 2fl+1
    const int node = (blockIdx.x * 256 + threadIdx.x) >> 5;
    const int deg  = g_deg[node];
    const int* __restrict__ cols = g_cols + (size_t)node * MAXDEG;

    for (int k = lane; k < deg; k += 32) scols[wid][k] = cols[k];
    __syncwarp();

    const float es = g_h2[node * 20 + 17];

    float ax = 0.f, ay = 0.f, ws = 0.f;
#pragma unroll 4
    for (int kb = 0; kb < deg; kb += 4) {
        int k = kb + j;
        bool valid = k < deg;
        int m = scols[wid][valid ? k : deg - 1];
        float2 hv = *reinterpret_cast<const float2*>(&g_h2[m * 20 + fl * 2]);
        float ed = g_h2[m * 20 + 16];   // broadcast load
        float e = es + ed; e = e > 0.f ? e : 0.2f * e;
        float w = __expf(e);
        if (valid) { ws += w; ax += w * hv.x; ay += w * hv.y; }
    }
#pragma unroll
    for (int o = 8; o <= 16; o <<= 1) {
        ax += __shfl_xor_sync(FULL, ax, o);
        ay += __shfl_xor_sync(FULL, ay, o);
        ws += __shfl_xor_sync(FULL, ws, o);
    }

    if (lane < 8) {   // j==0
        float inv = 1.f / ws;
        float vx = ax * inv, vy = ay * inv;
        sblk[wid][fl * 2]     = vx > 0.f ? vx : 0.f;
        sblk[wid][fl * 2 + 1] = vy > 0.f ? vy : 0.f;
    }
    __syncthreads();

    // per-block partial: 8 nodes -> 16 floats (fixed order)
    if (threadIdx.x < 16) {
        float p = 0.f;
#pragma unroll
        for (int w = 0; w < 8; w++) p += sblk[w][threadIdx.x];
        g_part[blockIdx.x * 16 + threadIdx.x] = p;
    }
    __threadfence();
    __syncthreads();
    __shared__ bool isLast;
    if (threadIdx.x == 0)
        isLast = (atomicAdd(&g_counter, 1) == GRID1 - 1);
    __syncthreads();
    if (isLast) {
        __threadfence();
        int f = threadIdx.x & 15, g = threadIdx.x >> 4;
        float s = 0.f;
        for (int b = g; b < GRID1; b += 16) s += g_part[b * 16 + f];
        __shared__ float red2[256];
        red2[threadIdx.x] = s;
        __syncthreads();
        if (threadIdx.x < 16) {
            float t = 0.f;
#pragma unroll
            for (int gg = 0; gg < 16; gg++) t += red2[gg * 16 + threadIdx.x];
            out[threadIdx.x] = t;
        }
        if (threadIdx.x == 0) g_counter = 0;   // reset for next replay
    }
}

// ---------------- launch ----------------------------------------------------
extern "C" void kernel_launch(void* const* d_in, const int* in_sizes, int n_in,
                              void* d_out, int out_size) {
    const float* x   = (const float*)d_in[0];
    const float* adj = (const float*)d_in[1];
    const float* W0  = (const float*)d_in[2];
    const float* a0s = (const float*)d_in[3];
    const float* a0d = (const float*)d_in[4];
    const float* W1  = (const float*)d_in[5];
    const float* a1s = (const float*)d_in[6];
    const float* a1d = (const float*)d_in[7];
    const float* W2  = (const float*)d_in[8];
    const float* a2s = (const float*)d_in[9];
    const float* a2d = (const float*)d_in[10];
    float* out = (float*)d_out;

    k_csr_lin0  <<<GRID1, 256>>>(x, adj, W0, a0s, a0d);
    k_attn0     <<<GRID1, 256>>>(W1, a1s, a1d);
    k_attn1     <<<GRID1, 256>>>(W2, a2s, a2d);
    k_attn_final<<<GRID1, 256>>>(out);
}

// round 7
// speedup vs baseline: 1.4595x; 1.0103x over previous
#include <cuda_runtime.h>
#include <cstdint>

#define NN     6144
#define MAXDEG 192
#define FULL   0xffffffffu
#define GRID1  768   // warp per node everywhere

// ---------------- scratch (device globals; no allocation allowed) -----------
__device__ int   g_deg[NN];
__device__ int   g_cols[NN * MAXDEG];
// layer0 row stride 16: [h0..h11, ed0, ed1, es0, es1]
// layer1 row stride 12: [h0..h5, ed0, ed1, es0, es1, pad, pad]
// layer2 row stride 20: [h0..h15, ed, es, pad, pad]
__device__ __align__(16) float g_h0[NN * 16];
__device__ __align__(16) float g_h1[NN * 12];
__device__ __align__(16) float g_h2[NN * 20];
__device__ float g_part[GRID1 * 16];
__device__ int   g_counter;   // zero-initialized

#define XOR_RED(v) { _Pragma("unroll") for (int _o = 16; _o > 0; _o >>= 1) (v) += __shfl_xor_sync(FULL, (v), _o); }

// ===================== K1: linear0 + CSR build (fused) =======================
__global__ void __launch_bounds__(256) k_csr_lin0(
    const float* __restrict__ x, const float* __restrict__ adj,
    const float* __restrict__ W0, const float* __restrict__ a0s,
    const float* __restrict__ a0d)
{
    __shared__ float sW[64 * 12];
    __shared__ float sa[24];
    for (int i = threadIdx.x; i < 768; i += 256) sW[i] = W0[i];
    if (threadIdx.x < 12) {
        sa[threadIdx.x]      = a0s[threadIdx.x];
        sa[12 + threadIdx.x] = a0d[threadIdx.x];
    }
    __syncthreads();

    const int node = (blockIdx.x * 256 + threadIdx.x) >> 5;
    const int lane = threadIdx.x & 31;

    // ---- linear0 ----
    float x0 = x[node * 64 + lane];
    float x1 = x[node * 64 + 32 + lane];
    float acc[12];
#pragma unroll
    for (int h = 0; h < 2; h++)
#pragma unroll
        for (int f = 0; f < 6; f++) {
            int hf = h * 6 + f;
            acc[hf] = x0 * sW[(h * 64 + lane) * 6 + f]
                    + x1 * sW[(h * 64 + lane + 32) * 6 + f];
        }
#pragma unroll
    for (int i = 0; i < 12; i++) XOR_RED(acc[i]);

    if (lane == 0) {
        float es0 = 0.f, ed0 = 0.f, es1 = 0.f, ed1 = 0.f;
#pragma unroll
        for (int f = 0; f < 6; f++) {
            es0 += acc[f]     * sa[f];       ed0 += acc[f]     * sa[12 + f];
            es1 += acc[6 + f] * sa[6 + f];   ed1 += acc[6 + f] * sa[18 + f];
        }
        float4* row = reinterpret_cast<float4*>(&g_h0[node * 16]);
        row[0] = make_float4(acc[0], acc[1], acc[2],  acc[3]);
        row[1] = make_float4(acc[4], acc[5], acc[6],  acc[7]);
        row[2] = make_float4(acc[8], acc[9], acc[10], acc[11]);
        row[3] = make_float4(ed0, ed1, es0, es1);
    }

    // ---- CSR build: 256 cols per iteration, 2 float4 in flight -------------
    const float4* a4 = reinterpret_cast<const float4*>(adj + (size_t)node * NN);
    int* outc = g_cols + (size_t)node * MAXDEG;
    int base = 0;
    const unsigned lt = (1u << lane) - 1u;
    float4 va = __ldg(&a4[lane]);
    float4 vb = __ldg(&a4[32 + lane]);
    for (int c0 = 0; c0 < NN; c0 += 256) {
        float4 na = {0,0,0,0}, nb = {0,0,0,0};
        if (c0 + 256 < NN) {
            na = __ldg(&a4[((c0 + 256) >> 2) + lane]);
            nb = __ldg(&a4[((c0 + 256) >> 2) + 32 + lane]);
        }
#pragma unroll
        for (int s = 0; s < 2; s++) {
            float4 v = s == 0 ? va : vb;
            bool n0 = v.x > 0.f, n1 = v.y > 0.f, n2 = v.z > 0.f, n3 = v.w > 0.f;
            unsigned any = __ballot_sync(FULL, n0 | n1 | n2 | n3);
            if (any) {
                int col0 = c0 + s * 128 + lane * 4;
                bool nz[4] = {n0, n1, n2, n3};
#pragma unroll
                for (int j = 0; j < 4; j++) {
                    unsigned m = __ballot_sync(FULL, nz[j]);
                    if (m) {
                        if (nz[j]) {
                            int p = base + __popc(m & lt);
                            if (p < MAXDEG) outc[p] = col0 + j;
                        }
                        base += __popc(m);
                    }
                }
            }
        }
        va = na; vb = nb;
    }
    if (lane == 0) g_deg[node] = base < MAXDEG ? base : MAXDEG;
}

// ======== K2: attn layer0 (H=2,F=6) + elu + linear1 -> g_h1 ==================
// Warp per node; 8 neighbors x 4 float4-lanes per iteration.
__global__ void __launch_bounds__(256) k_attn0(
    const float* __restrict__ W1, const float* __restrict__ a1s,
    const float* __restrict__ a1d)
{
    __shared__ float sW[72];        // [2][12][3]
    __shared__ float sa[12];
    __shared__ float shx[8][16];
    __shared__ float shh[8][8];
    __shared__ int   scols[8][MAXDEG];
    if (threadIdx.x < 72) sW[threadIdx.x] = W1[threadIdx.x];
    if (threadIdx.x < 6) {
        sa[threadIdx.x]     = a1s[threadIdx.x];
        sa[6 + threadIdx.x] = a1d[threadIdx.x];
    }
    __syncthreads();

    const int lane = threadIdx.x & 31;
    const int wid  = threadIdx.x >> 5;
    const int j    = lane >> 2;        // 0..7 neighbor slot
    const int fl   = lane & 3;         // float4 slot: features 4fl..4fl+3
    const int node = (blockIdx.x * 256 + threadIdx.x) >> 5;
    const int deg  = g_deg[node];
    const int* __restrict__ cols = g_cols + (size_t)node * MAXDEG;

    for (int k = lane; k < deg; k += 32) scols[wid][k] = cols[k];
    __syncwarp();

    const float es0 = g_h0[node * 16 + 14];
    const float es1 = g_h0[node * 16 + 15];
    // per-component head selectors (lane-constant, hoisted)
    const int f0 = fl * 4;

    float4 a = {0.f, 0.f, 0.f, 0.f};
    float ws0 = 0.f, ws1 = 0.f;
#pragma unroll 2
    for (int kb = 0; kb < deg; kb += 8) {
        int k = kb + j;
        bool valid = k < deg;
        int m = scols[wid][valid ? k : deg - 1];
        float4 hv = *reinterpret_cast<const float4*>(&g_h0[m * 16 + f0]);
        float ed0 = __shfl_sync(FULL, hv.x, 3, 4);   // fl=3 holds [ed0,ed1,es0,es1]
        float ed1 = __shfl_sync(FULL, hv.y, 3, 4);
        float e0 = es0 + ed0; e0 = e0 > 0.f ? e0 : 0.2f * e0;
        float e1 = es1 + ed1; e1 = e1 > 0.f ? e1 : 0.2f * e1;
        float w0 = __expf(e0), w1 = __expf(e1);
        if (valid) {
            ws0 += w0; ws1 += w1;
            float wx = f0     < 6 ? w0 : (f0     < 12 ? w1 : 0.f);
            float wy = f0 + 1 < 6 ? w0 : (f0 + 1 < 12 ? w1 : 0.f);
            float wz = f0 + 2 < 6 ? w0 : (f0 + 2 < 12 ? w1 : 0.f);
            float ww = f0 + 3 < 6 ? w0 : (f0 + 3 < 12 ? w1 : 0.f);
            a.x += wx * hv.x; a.y += wy * hv.y;
            a.z += wz * hv.z; a.w += ww * hv.w;
        }
    }
    // merge over neighbor-slot bits (2,3,4); fl bits stay distinct
#pragma unroll
    for (int o = 4; o <= 16; o <<= 1) {
        a.x += __shfl_xor_sync(FULL, a.x, o);
        a.y += __shfl_xor_sync(FULL, a.y, o);
        a.z += __shfl_xor_sync(FULL, a.z, o);
        a.w += __shfl_xor_sync(FULL, a.w, o);
        ws0 += __shfl_xor_sync(FULL, ws0, o);
        ws1 += __shfl_xor_sync(FULL, ws1, o);
    }

    if (lane < 3) {   // j==0, fl=0..2: features 4fl..4fl+3 (<12)
        float inv0 = 1.f / ws0, inv1 = 1.f / ws1;
        float v0 = a.x * (f0     < 6 ? inv0 : inv1);
        float v1 = a.y * (f0 + 1 < 6 ? inv0 : inv1);
        float v2 = a.z * (f0 + 2 < 6 ? inv0 : inv1);
        float v3 = a.w * (f0 + 3 < 6 ? inv0 : inv1);
        shx[wid][f0]     = v0 > 0.f ? v0 : expm1f(v0);
        shx[wid][f0 + 1] = v1 > 0.f ? v1 : expm1f(v1);
        shx[wid][f0 + 2] = v2 > 0.f ? v2 : expm1f(v2);
        shx[wid][f0 + 3] = v3 > 0.f ? v3 : expm1f(v3);
    }
    __syncwarp();
    if (lane < 6) {
        int h2 = lane / 3, f2 = lane % 3;
        float s = 0.f;
#pragma unroll
        for (int i = 0; i < 12; i++) s += shx[wid][i] * sW[(h2 * 12 + i) * 3 + f2];
        g_h1[node * 12 + lane] = s;
        shh[wid][lane] = s;
    }
    __syncwarp();
    if (lane < 2) {
        float es = 0.f, ed = 0.f;
#pragma unroll
        for (int f2 = 0; f2 < 3; f2++) {
            float hv = shh[wid][lane * 3 + f2];
            es += hv * sa[lane * 3 + f2];
            ed += hv * sa[6 + lane * 3 + f2];
        }
        g_h1[node * 12 + 6 + lane] = ed;
        g_h1[node * 12 + 8 + lane] = es;
    }
}

// ======== K3: attn layer1 (H=2,F=3) + elu + linear2 -> g_h2 ==================
// Warp per node; 16 neighbors x 2 float4-lanes per iteration.
__global__ void __launch_bounds__(256) k_attn1(
    const float* __restrict__ W2, const float* __restrict__ a2s,
    const float* __restrict__ a2d)
{
    __shared__ float sW[96];        // [6][16]
    __shared__ float sa2[32];       // a2d(16), a2s(16)
    __shared__ float shx[8][8];
    __shared__ float shh[8][16];
    __shared__ int   scols[8][MAXDEG];
    if (threadIdx.x < 96) sW[threadIdx.x] = W2[threadIdx.x];
    if (threadIdx.x < 16) {
        sa2[threadIdx.x]      = a2d[threadIdx.x];
        sa2[16 + threadIdx.x] = a2s[threadIdx.x];
    }
    __syncthreads();

    const int lane = threadIdx.x & 31;
    const int wid  = threadIdx.x >> 5;
    const int j    = lane >> 1;        // 0..15 neighbor slot
    const int fl   = lane & 1;         // float4 slot: floats 4fl..4fl+3
    const int node = (blockIdx.x * 256 + threadIdx.x) >> 5;
    const int deg  = g_deg[node];
    const int* __restrict__ cols = g_cols + (size_t)node * MAXDEG;

    for (int k = lane; k < deg; k += 32) scols[wid][k] = cols[k];
    __syncwarp();

    const float es0 = g_h1[node * 12 + 8];
    const float es1 = g_h1[node * 12 + 9];

    float4 a = {0.f, 0.f, 0.f, 0.f};
    float ws0 = 0.f, ws1 = 0.f;
#pragma unroll 2
    for (int kb = 0; kb < deg; kb += 16) {
        int k = kb + j;
        bool valid = k < deg;
        int m = scols[wid][valid ? k : deg - 1];
        float4 hv = *reinterpret_cast<const float4*>(&g_h1[m * 12 + fl * 4]);
        float ed0 = __shfl_sync(FULL, hv.z, 1, 2);   // fl=1 holds [f4,f5,ed0,ed1]
        float ed1 = __shfl_sync(FULL, hv.w, 1, 2);
        float e0 = es0 + ed0; e0 = e0 > 0.f ? e0 : 0.2f * e0;
        float e1 = es1 + ed1; e1 = e1 > 0.f ? e1 : 0.2f * e1;
        float w0 = __expf(e0), w1 = __expf(e1);
        if (valid) {
            ws0 += w0; ws1 += w1;
            if (fl == 0) {            // f0,f1,f2 head0; f3 head1
                a.x += w0 * hv.x; a.y += w0 * hv.y;
                a.z += w0 * hv.z; a.w += w1 * hv.w;
            } else {                  // f4,f5 head1; f6,f7 = ed (excluded)
                a.x += w1 * hv.x; a.y += w1 * hv.y;
            }
        }
    }
    // merge over neighbor-slot bits (1..4); fl bit stays distinct
#pragma unroll
    for (int o = 2; o <= 16; o <<= 1) {
        a.x += __shfl_xor_sync(FULL, a.x, o);
        a.y += __shfl_xor_sync(FULL, a.y, o);
        a.z += __shfl_xor_sync(FULL, a.z, o);
        a.w += __shfl_xor_sync(FULL, a.w, o);
        ws0 += __shfl_xor_sync(FULL, ws0, o);
        ws1 += __shfl_xor_sync(FULL, ws1, o);
    }

    if (lane < 2) {
        float inv0 = 1.f / ws0, inv1 = 1.f / ws1;
        if (lane == 0) {
            float v0 = a.x * inv0, v1 = a.y * inv0, v2 = a.z * inv0, v3 = a.w * inv1;
            shx[wid][0] = v0 > 0.f ? v0 : expm1f(v0);
            shx[wid][1] = v1 > 0.f ? v1 : expm1f(v1);
            shx[wid][2] = v2 > 0.f ? v2 : expm1f(v2);
            shx[wid][3] = v3 > 0.f ? v3 : expm1f(v3);
        } else {
            float v4 = a.x * inv1, v5 = a.y * inv1;
            shx[wid][4] = v4 > 0.f ? v4 : expm1f(v4);
            shx[wid][5] = v5 > 0.f ? v5 : expm1f(v5);
        }
    }
    __syncwarp();
    if (lane < 16) {
        float s = 0.f;
#pragma unroll
        for (int i = 0; i < 6; i++) s += shx[wid][i] * sW[i * 16 + lane];
        g_h2[node * 20 + lane] = s;
        shh[wid][lane] = s;
    }
    __syncwarp();
    if (lane < 2) {
        float d = 0.f;
#pragma unroll
        for (int f = 0; f < 16; f++) d += shh[wid][f] * sa2[lane * 16 + f];
        g_h2[node * 20 + 16 + lane] = d;   // 16 = ed, 17 = es
    }
}

// ===== K4: final attn (H=1,F=16) + relu + hierarchical deterministic sum =====
// Warp per node; 8 neighbors x 4 float4-lanes per iteration.
__global__ void __launch_bounds__(256) k_attn_final(float* __restrict__ out)
{
    __shared__ float sblk[8][16];
    __shared__ int   scols[8][MAXDEG];
    const int lane = threadIdx.x & 31;
    const int wid  = threadIdx.x >> 5;
    const int j    = lane >> 2;        // 0..7 neighbor slot
    const int fl   = lane & 3;         // features 4fl..4fl+3
    const int node = (blockIdx.x * 256 + threadIdx.x) >> 5;
    const int deg  = g_deg[node];
    const int* __restrict__ cols = g_cols + (size_t)node * MAXDEG;

    for (int k = lane; k < deg; k += 32) scols[wid][k] = cols[k];
    __syncwarp();

    const float es = g_h2[node * 20 + 17];

    float4 a = {0.f, 0.f, 0.f, 0.f};
    float ws = 0.f;
#pragma unroll 2
    for (int kb = 0; kb < deg; kb += 8) {
        int k = kb + j;
        bool valid = k < deg;
        int m = scols[wid][valid ? k : deg - 1];
        float4 hv = *reinterpret_cast<const float4*>(&g_h2[m * 20 + fl * 4]);
        float ed = g_h2[m * 20 + 16];   // broadcast within 4-lane group
        float e = es + ed; e = e > 0.f ? e : 0.2f * e;
        float w = __expf(e);
        if (valid) {
            ws += w;
            a.x += w * hv.x; a.y += w * hv.y;
            a.z += w * hv.z; a.w += w * hv.w;
        }
    }
#pragma unroll
    for (int o = 4; o <= 16; o <<= 1) {
        a.x += __shfl_xor_sync(FULL, a.x, o);
        a.y += __shfl_xor_sync(FULL, a.y, o);
        a.z += __shfl_xor_sync(FULL, a.z, o);
        a.w += __shfl_xor_sync(FULL, a.w, o);
        ws  += __shfl_xor_sync(FULL, ws, o);
    }

    if (lane < 4) {   // j==0
        float inv = 1.f / ws;
        float v0 = a.x * inv, v1 = a.y * inv, v2 = a.z * inv, v3 = a.w * inv;
        sblk[wid][fl * 4]     = v0 > 0.f ? v0 : 0.f;
        sblk[wid][fl * 4 + 1] = v1 > 0.f ? v1 : 0.f;
        sblk[wid][fl * 4 + 2] = v2 > 0.f ? v2 : 0.f;
        sblk[wid][fl * 4 + 3] = v3 > 0.f ? v3 : 0.f;
    }
    __syncthreads();

    // per-block partial: 8 nodes -> 16 floats (fixed order)
    if (threadIdx.x < 16) {
        float p = 0.f;
#pragma unroll
        for (int w = 0; w < 8; w++) p += sblk[w][threadIdx.x];
        g_part[blockIdx.x * 16 + threadIdx.x] = p;
    }
    __threadfence();
    __syncthreads();
    __shared__ bool isLast;
    if (threadIdx.x == 0)
        isLast = (atomicAdd(&g_counter, 1) == GRID1 - 1);
    __syncthreads();
    if (isLast) {
        __threadfence();
        int f = threadIdx.x & 15, g = threadIdx.x >> 4;
        float s = 0.f;
        for (int b = g; b < GRID1; b += 16) s += g_part[b * 16 + f];
        __shared__ float red2[256];
        red2[threadIdx.x] = s;
        __syncthreads();
        if (threadIdx.x < 16) {
            float t = 0.f;
#pragma unroll
            for (int gg = 0; gg < 16; gg++) t += red2[gg * 16 + threadIdx.x];
            out[threadIdx.x] = t;
        }
        if (threadIdx.x == 0) g_counter = 0;   // reset for next replay
    }
}

// ---------------- launch ----------------------------------------------------
extern "C" void kernel_launch(void* const* d_in, const int* in_sizes, int n_in,
                              void* d_out, int out_size) {
    const float* x   = (const float*)d_in[0];
    const float* adj = (const float*)d_in[1];
    const float* W0  = (const float*)d_in[2];
    const float* a0s = (const float*)d_in[3];
    const float* a0d = (const float*)d_in[4];
    const float* W1  = (const float*)d_in[5];
    const float* a1s = (const float*)d_in[6];
    const float* a1d = (const float*)d_in[7];
    const float* W2  = (const float*)d_in[8];
    const float* a2s = (const float*)d_in[9];
    const float* a2d = (const float*)d_in[10];
    float* out = (float*)d_out;

    k_csr_lin0  <<<GRID1, 256>>>(x, adj, W0, a0s, a0d);
    k_attn0     <<<GRID1, 256>>>(W1, a1s, a1d);
    k_attn1     <<<GRID1, 256>>>(W2, a2s, a2d);
    k_attn_final<<<GRID1, 256>>>(out);
}

// round 8
// speedup vs baseline: 1.4815x; 1.0150x over previous
#include <cuda_runtime.h>
#include <cstdint>

#define NN     6144
#define MAXDEG 192
#define FULL   0xffffffffu
#define GRID   768

// ---------------- scratch (device globals; no allocation allowed) -----------
// layer0 row stride 16: [h0..h11, ed0, ed1, es0, es1]
// layer1 row stride 12: [h0..h5, ed0, ed1, pad...]
// layer2 row stride 20: [h0..h15, ed, pad...]
__device__ __align__(16) float g_h0[NN * 16];
__device__ __align__(16) float g_h1[NN * 12];
__device__ __align__(16) float g_h2[NN * 20];
__device__ float g_part[GRID * 16];
__device__ int   g_barc[3];   // zero-initialized
__device__ int   g_barf[3];   // zero-initialized
__device__ int   g_exit;      // zero-initialized

#define XOR_RED(v) { _Pragma("unroll") for (int _o = 16; _o > 0; _o >>= 1) (v) += __shfl_xor_sync(FULL, (v), _o); }

__device__ __forceinline__ void grid_barrier(int id) {
    __syncthreads();
    if (threadIdx.x == 0) {
        __threadfence();
        if (atomicAdd(&g_barc[id], 1) == GRID - 1) {
            g_barc[id] = 0;                 // all arrived; nobody reads it again
            __threadfence();
            atomicExch(&g_barf[id], 1);     // release
        } else {
            while (atomicAdd(&g_barf[id], 0) == 0) {}
        }
        __threadfence();
    }
    __syncthreads();
}

// ======================= single fused persistent kernel ======================
__global__ void __launch_bounds__(256, 6) k_gat(
    const float* __restrict__ x,   const float* __restrict__ adj,
    const float* __restrict__ W0,  const float* __restrict__ a0s, const float* __restrict__ a0d,
    const float* __restrict__ W1,  const float* __restrict__ a1s, const float* __restrict__ a1d,
    const float* __restrict__ W2,  const float* __restrict__ a2s, const float* __restrict__ a2d,
    float* __restrict__ out)
{
    __shared__ float sW0[768];
    __shared__ float sa0[24];
    __shared__ float sW1[72];
    __shared__ float sa1[12];
    __shared__ float sW2[96];
    __shared__ float sa2[32];
    __shared__ int   scols[8][MAXDEG];
    __shared__ float shx[8][16];
    __shared__ float shh[8][16];
    __shared__ float sblk[8][16];

    // ---- load all weights once ----
    for (int i = threadIdx.x; i < 768; i += 256) sW0[i] = W0[i];
    {
        int t = threadIdx.x;
        if (t < 12)  { sa0[t] = a0s[t]; sa0[12 + t] = a0d[t]; }
        if (t >= 32  && t < 104) sW1[t - 32]  = W1[t - 32];
        if (t >= 104 && t < 110) sa1[t - 104] = a1s[t - 104];
        if (t >= 110 && t < 116) sa1[6 + t - 110] = a1d[t - 110];
        if (t >= 128 && t < 224) sW2[t - 128] = W2[t - 128];
        if (t >= 224 && t < 240) sa2[t - 224] = a2d[t - 224];
        if (t >= 240 && t < 256) sa2[16 + t - 240] = a2s[t - 240];
    }
    __syncthreads();

    const int lane = threadIdx.x & 31;
    const int wid  = threadIdx.x >> 5;
    const int node = blockIdx.x * 8 + wid;

    // ============ PHASE 0: linear0 + CSR scan (cols -> smem) ================
    float es0_0 = 0.f, es1_0 = 0.f;   // layer-0 source logits (broadcast later)
    {
        float x0 = x[node * 64 + lane];
        float x1 = x[node * 64 + 32 + lane];
        float acc[12];
#pragma unroll
        for (int h = 0; h < 2; h++)
#pragma unroll
            for (int f = 0; f < 6; f++) {
                int hf = h * 6 + f;
                acc[hf] = x0 * sW0[(h * 64 + lane) * 6 + f]
                        + x1 * sW0[(h * 64 + lane + 32) * 6 + f];
            }
#pragma unroll
        for (int i = 0; i < 12; i++) XOR_RED(acc[i]);

        if (lane == 0) {
            float ed0 = 0.f, ed1 = 0.f;
#pragma unroll
            for (int f = 0; f < 6; f++) {
                es0_0 += acc[f]     * sa0[f];       ed0 += acc[f]     * sa0[12 + f];
                es1_0 += acc[6 + f] * sa0[6 + f];   ed1 += acc[6 + f] * sa0[18 + f];
            }
            float4* row = reinterpret_cast<float4*>(&g_h0[node * 16]);
            row[0] = make_float4(acc[0], acc[1], acc[2],  acc[3]);
            row[1] = make_float4(acc[4], acc[5], acc[6],  acc[7]);
            row[2] = make_float4(acc[8], acc[9], acc[10], acc[11]);
            row[3] = make_float4(ed0, ed1, es0_0, es1_0);
        }
        es0_0 = __shfl_sync(FULL, es0_0, 0);
        es1_0 = __shfl_sync(FULL, es1_0, 0);
    }

    int deg;
    {
        const float4* a4 = reinterpret_cast<const float4*>(adj + (size_t)node * NN);
        int base = 0;
        const unsigned lt = (1u << lane) - 1u;
        float4 va = __ldg(&a4[lane]);
        float4 vb = __ldg(&a4[32 + lane]);
        for (int c0 = 0; c0 < NN; c0 += 256) {
            float4 na = {0,0,0,0}, nb = {0,0,0,0};
            if (c0 + 256 < NN) {
                na = __ldg(&a4[((c0 + 256) >> 2) + lane]);
                nb = __ldg(&a4[((c0 + 256) >> 2) + 32 + lane]);
            }
#pragma unroll
            for (int s = 0; s < 2; s++) {
                float4 v = s == 0 ? va : vb;
                bool n0 = v.x > 0.f, n1 = v.y > 0.f, n2 = v.z > 0.f, n3 = v.w > 0.f;
                unsigned any = __ballot_sync(FULL, n0 | n1 | n2 | n3);
                if (any) {
                    int col0 = c0 + s * 128 + lane * 4;
                    bool nz[4] = {n0, n1, n2, n3};
#pragma unroll
                    for (int j = 0; j < 4; j++) {
                        unsigned m = __ballot_sync(FULL, nz[j]);
                        if (m) {
                            if (nz[j]) {
                                int p = base + __popc(m & lt);
                                if (p < MAXDEG) scols[wid][p] = col0 + j;
                            }
                            base += __popc(m);
                        }
                    }
                }
            }
            va = na; vb = nb;
        }
        deg = base < MAXDEG ? base : MAXDEG;
    }

    grid_barrier(0);

    // ============ PHASE 1: attn layer0 (H=2,F=6) + elu + linear1 ============
    float es0_1 = 0.f, es1_1 = 0.f;
    {
        const int j  = lane >> 2;      // neighbor slot 0..7
        const int fl = lane & 3;       // float4 slot
        const int f0 = fl * 4;

        float4 a = {0.f, 0.f, 0.f, 0.f};
        float ws0 = 0.f, ws1 = 0.f;
#pragma unroll 2
        for (int kb = 0; kb < deg; kb += 8) {
            int k = kb + j;
            bool valid = k < deg;
            int m = scols[wid][valid ? k : deg - 1];
            float4 hv = *reinterpret_cast<const float4*>(&g_h0[m * 16 + f0]);
            float ed0 = __shfl_sync(FULL, hv.x, 3, 4);   // fl=3 holds [ed0,ed1,es0,es1]
            float ed1 = __shfl_sync(FULL, hv.y, 3, 4);
            float e0 = es0_0 + ed0; e0 = e0 > 0.f ? e0 : 0.2f * e0;
            float e1 = es1_0 + ed1; e1 = e1 > 0.f ? e1 : 0.2f * e1;
            float w0 = __expf(e0), w1 = __expf(e1);
            if (valid) {
                ws0 += w0; ws1 += w1;
                float wx = f0     < 6 ? w0 : (f0     < 12 ? w1 : 0.f);
                float wy = f0 + 1 < 6 ? w0 : (f0 + 1 < 12 ? w1 : 0.f);
                float wz = f0 + 2 < 6 ? w0 : (f0 + 2 < 12 ? w1 : 0.f);
                float ww = f0 + 3 < 6 ? w0 : (f0 + 3 < 12 ? w1 : 0.f);
                a.x += wx * hv.x; a.y += wy * hv.y;
                a.z += wz * hv.z; a.w += ww * hv.w;
            }
        }
#pragma unroll
        for (int o = 4; o <= 16; o <<= 1) {
            a.x += __shfl_xor_sync(FULL, a.x, o);
            a.y += __shfl_xor_sync(FULL, a.y, o);
            a.z += __shfl_xor_sync(FULL, a.z, o);
            a.w += __shfl_xor_sync(FULL, a.w, o);
            ws0 += __shfl_xor_sync(FULL, ws0, o);
            ws1 += __shfl_xor_sync(FULL, ws1, o);
        }

        if (lane < 3) {
            float inv0 = 1.f / ws0, inv1 = 1.f / ws1;
            float v0 = a.x * (f0     < 6 ? inv0 : inv1);
            float v1 = a.y * (f0 + 1 < 6 ? inv0 : inv1);
            float v2 = a.z * (f0 + 2 < 6 ? inv0 : inv1);
            float v3 = a.w * (f0 + 3 < 6 ? inv0 : inv1);
            shx[wid][f0]     = v0 > 0.f ? v0 : expm1f(v0);
            shx[wid][f0 + 1] = v1 > 0.f ? v1 : expm1f(v1);
            shx[wid][f0 + 2] = v2 > 0.f ? v2 : expm1f(v2);
            shx[wid][f0 + 3] = v3 > 0.f ? v3 : expm1f(v3);
        }
        __syncwarp();
        if (lane < 6) {
            int h2 = lane / 3, f2 = lane % 3;
            float s = 0.f;
#pragma unroll
            for (int i = 0; i < 12; i++) s += shx[wid][i] * sW1[(h2 * 12 + i) * 3 + f2];
            g_h1[node * 12 + lane] = s;
            shh[wid][lane] = s;
        }
        __syncwarp();
        float es_l = 0.f;
        if (lane < 2) {
            float ed = 0.f;
#pragma unroll
            for (int f2 = 0; f2 < 3; f2++) {
                float hv = shh[wid][lane * 3 + f2];
                es_l += hv * sa1[lane * 3 + f2];
                ed   += hv * sa1[6 + lane * 3 + f2];
            }
            g_h1[node * 12 + 6 + lane] = ed;    // slots 6,7 = ed0,ed1
        }
        es0_1 = __shfl_sync(FULL, es_l, 0);
        es1_1 = __shfl_sync(FULL, es_l, 1);
    }

    grid_barrier(1);

    // ============ PHASE 2: attn layer1 (H=2,F=3) + elu + linear2 ============
    float es_2 = 0.f;
    {
        const int j  = lane >> 1;      // neighbor slot 0..15
        const int fl = lane & 1;

        float4 a = {0.f, 0.f, 0.f, 0.f};
        float ws0 = 0.f, ws1 = 0.f;
#pragma unroll 2
        for (int kb = 0; kb < deg; kb += 16) {
            int k = kb + j;
            bool valid = k < deg;
            int m = scols[wid][valid ? k : deg - 1];
            float4 hv = *reinterpret_cast<const float4*>(&g_h1[m * 12 + fl * 4]);
            float ed0 = __shfl_sync(FULL, hv.z, 1, 2);   // fl=1 holds [f4,f5,ed0,ed1]
            float ed1 = __shfl_sync(FULL, hv.w, 1, 2);
            float e0 = es0_1 + ed0; e0 = e0 > 0.f ? e0 : 0.2f * e0;
            float e1 = es1_1 + ed1; e1 = e1 > 0.f ? e1 : 0.2f * e1;
            float w0 = __expf(e0), w1 = __expf(e1);
            if (valid) {
                ws0 += w0; ws1 += w1;
                if (fl == 0) {            // f0,f1,f2 head0; f3 head1
                    a.x += w0 * hv.x; a.y += w0 * hv.y;
                    a.z += w0 * hv.z; a.w += w1 * hv.w;
                } else {                  // f4,f5 head1
                    a.x += w1 * hv.x; a.y += w1 * hv.y;
                }
            }
        }
#pragma unroll
        for (int o = 2; o <= 16; o <<= 1) {
            a.x += __shfl_xor_sync(FULL, a.x, o);
            a.y += __shfl_xor_sync(FULL, a.y, o);
            a.z += __shfl_xor_sync(FULL, a.z, o);
            a.w += __shfl_xor_sync(FULL, a.w, o);
            ws0 += __shfl_xor_sync(FULL, ws0, o);
            ws1 += __shfl_xor_sync(FULL, ws1, o);
        }

        if (lane < 2) {
            float inv0 = 1.f / ws0, inv1 = 1.f / ws1;
            if (lane == 0) {
                float v0 = a.x * inv0, v1 = a.y * inv0, v2 = a.z * inv0, v3 = a.w * inv1;
                shx[wid][0] = v0 > 0.f ? v0 : expm1f(v0);
                shx[wid][1] = v1 > 0.f ? v1 : expm1f(v1);
                shx[wid][2] = v2 > 0.f ? v2 : expm1f(v2);
                shx[wid][3] = v3 > 0.f ? v3 : expm1f(v3);
            } else {
                float v4 = a.x * inv1, v5 = a.y * inv1;
                shx[wid][4] = v4 > 0.f ? v4 : expm1f(v4);
                shx[wid][5] = v5 > 0.f ? v5 : expm1f(v5);
            }
        }
        __syncwarp();
        if (lane < 16) {
            float s = 0.f;
#pragma unroll
            for (int i = 0; i < 6; i++) s += shx[wid][i] * sW2[i * 16 + lane];
            g_h2[node * 20 + lane] = s;
            shh[wid][lane] = s;
        }
        __syncwarp();
        float d_l = 0.f;
        if (lane < 2) {
#pragma unroll
            for (int f = 0; f < 16; f++) d_l += shh[wid][f] * sa2[lane * 16 + f];
            if (lane == 0) g_h2[node * 20 + 16] = d_l;   // ed (gathered by neighbors)
        }
        es_2 = __shfl_sync(FULL, d_l, 1);                // es stays in registers
    }

    grid_barrier(2);

    // ===== PHASE 3: final attn (H=1,F=16) + relu + deterministic sum ========
    {
        const int j  = lane >> 2;      // neighbor slot 0..7
        const int fl = lane & 3;

        float4 a = {0.f, 0.f, 0.f, 0.f};
        float ws = 0.f;
#pragma unroll 2
        for (int kb = 0; kb < deg; kb += 8) {
            int k = kb + j;
            bool valid = k < deg;
            int m = scols[wid][valid ? k : deg - 1];
            float4 hv = *reinterpret_cast<const float4*>(&g_h2[m * 20 + fl * 4]);
            float ed = g_h2[m * 20 + 16];
            float e = es_2 + ed; e = e > 0.f ? e : 0.2f * e;
            float w = __expf(e);
            if (valid) {
                ws += w;
                a.x += w * hv.x; a.y += w * hv.y;
                a.z += w * hv.z; a.w += w * hv.w;
            }
        }
#pragma unroll
        for (int o = 4; o <= 16; o <<= 1) {
            a.x += __shfl_xor_sync(FULL, a.x, o);
            a.y += __shfl_xor_sync(FULL, a.y, o);
            a.z += __shfl_xor_sync(FULL, a.z, o);
            a.w += __shfl_xor_sync(FULL, a.w, o);
            ws  += __shfl_xor_sync(FULL, ws, o);
        }

        if (lane < 4) {
            float inv = 1.f / ws;
            float v0 = a.x * inv, v1 = a.y * inv, v2 = a.z * inv, v3 = a.w * inv;
            sblk[wid][fl * 4]     = v0 > 0.f ? v0 : 0.f;
            sblk[wid][fl * 4 + 1] = v1 > 0.f ? v1 : 0.f;
            sblk[wid][fl * 4 + 2] = v2 > 0.f ? v2 : 0.f;
            sblk[wid][fl * 4 + 3] = v3 > 0.f ? v3 : 0.f;
        }
    }
    __syncthreads();

    if (threadIdx.x < 16) {
        float p = 0.f;
#pragma unroll
        for (int w = 0; w < 8; w++) p += sblk[w][threadIdx.x];
        g_part[blockIdx.x * 16 + threadIdx.x] = p;
    }
    __threadfence();
    __syncthreads();
    __shared__ bool isLast;
    if (threadIdx.x == 0)
        isLast = (atomicAdd(&g_exit, 1) == GRID - 1);
    __syncthreads();
    if (isLast) {
        __threadfence();
        int f = threadIdx.x & 15, g = threadIdx.x >> 4;
        float s = 0.f;
        for (int b = g; b < GRID; b += 16) s += g_part[b * 16 + f];
        __shared__ float red2[256];
        red2[threadIdx.x] = s;
        __syncthreads();
        if (threadIdx.x < 16) {
            float t = 0.f;
#pragma unroll
            for (int gg = 0; gg < 16; gg++) t += red2[gg * 16 + threadIdx.x];
            out[threadIdx.x] = t;
        }
        if (threadIdx.x == 0) {      // reset ALL sync state for next replay
            g_barf[0] = 0; g_barf[1] = 0; g_barf[2] = 0;
            g_exit = 0;
            __threadfence();
        }
    }
}

// ---------------- launch ----------------------------------------------------
extern "C" void kernel_launch(void* const* d_in, const int* in_sizes, int n_in,
                              void* d_out, int out_size) {
    const float* x   = (const float*)d_in[0];
    const float* adj = (const float*)d_in[1];
    const float* W0  = (const float*)d_in[2];
    const float* a0s = (const float*)d_in[3];
    const float* a0d = (const float*)d_in[4];
    const float* W1  = (const float*)d_in[5];
    const float* a1s = (const float*)d_in[6];
    const float* a1d = (const float*)d_in[7];
    const float* W2  = (const float*)d_in[8];
    const float* a2s = (const float*)d_in[9];
    const float* a2d = (const float*)d_in[10];
    float* out = (float*)d_out;

    k_gat<<<GRID, 256>>>(x, adj, W0, a0s, a0d, W1, a1s, a1d, W2, a2s, a2d, out);
}